// round 4
// baseline (speedup 1.0000x reference)
#include <cuda_runtime.h>
#include <cuda_fp16.h>
#include <cstdint>

// ============================================================================
// B=8, N=4096, D=256, QK=128, M=32
//   Q = H0 @ Wq ; K = X0 @ Wk      (f16)
//   sumexp[b,n] = sum_m exp(scale * Q[b,n,:]·K[b,m,:])
//   w_keep = sumexp / sum(sumexp)
//   slot_w = softmax(slot_logits); w = slot_w*w_keep; w /= (sum+1e-6)
//   out = w @ H0
// R4: sumexp pipelined — f16 MMA accumulators (half regs) enable double-
//     buffered accumulator sets; exp of chunk j-1 interleaved into MMA of
//     chunk j so MUFU hides under tensor. One barrier per chunk.
// ============================================================================

#define Bdim 8
#define Ndim 4096
#define Ddim 256
#define QKdim 128
#define Mdim 32

__device__ __half g_Qh[Bdim * Ndim * QKdim];
__device__ __half g_Kh[Bdim * Ndim * QKdim];
__device__ __half g_Wt[2][QKdim * Ddim];
__device__ float g_sumexp[Bdim * Ndim];
__device__ float g_wkeep[Bdim * Ndim];
__device__ float g_slotw[Mdim * Ndim];
__device__ float g_norm[Bdim * Mdim];
__device__ float g_part[Bdim * 32 * Mdim * Ddim];

// ---------------------------------------------------------------------------
// helpers
// ---------------------------------------------------------------------------
__device__ __forceinline__ uint32_t smem_u32(const void* p) {
    uint32_t a;
    asm("{ .reg .u64 t; cvta.to.shared.u64 t, %1; cvt.u32.u64 %0, t; }" : "=r"(a) : "l"(p));
    return a;
}
__device__ __forceinline__ float ex2f(float x) {
    float r; asm("ex2.approx.ftz.f32 %0, %1;" : "=f"(r) : "f"(x)); return r;
}
#define CP_ASYNC16(dst, src) \
    asm volatile("cp.async.cg.shared.global [%0], [%1], 16;" :: "r"(dst), "l"(src))
#define CP_COMMIT() asm volatile("cp.async.commit_group;" ::: "memory")
#define CP_WAIT1()  asm volatile("cp.async.wait_group 1;" ::: "memory")
#define CP_WAIT0()  asm volatile("cp.async.wait_group 0;" ::: "memory")

__device__ __forceinline__ void ldsm_x4(uint32_t* r, uint32_t addr) {
    asm volatile("ldmatrix.sync.aligned.m8n8.x4.shared.b16 {%0,%1,%2,%3}, [%4];"
                 : "=r"(r[0]), "=r"(r[1]), "=r"(r[2]), "=r"(r[3]) : "r"(addr));
}
// f16 in, f32 acc (projection)
__device__ __forceinline__ void mma_f32acc(float* c, const uint32_t* a, const uint32_t* b) {
    asm volatile(
        "mma.sync.aligned.m16n8k16.row.col.f32.f16.f16.f32 "
        "{%0,%1,%2,%3}, {%4,%5,%6,%7}, {%8,%9}, {%0,%1,%2,%3};"
        : "+f"(c[0]), "+f"(c[1]), "+f"(c[2]), "+f"(c[3])
        : "r"(a[0]), "r"(a[1]), "r"(a[2]), "r"(a[3]), "r"(b[0]), "r"(b[1]));
}
// f16 in, f16 acc (S kernel): init (C=0) and accumulate variants
__device__ __forceinline__ void mma_f16_init(uint32_t* d, const uint32_t* a, const uint32_t* b) {
    asm volatile(
        "mma.sync.aligned.m16n8k16.row.col.f16.f16.f16.f16 "
        "{%0,%1}, {%2,%3,%4,%5}, {%6,%7}, {%8,%9};"
        : "=r"(d[0]), "=r"(d[1])
        : "r"(a[0]), "r"(a[1]), "r"(a[2]), "r"(a[3]), "r"(b[0]), "r"(b[1]),
          "r"(0u), "r"(0u));
}
__device__ __forceinline__ void mma_f16_acc(uint32_t* d, const uint32_t* a, const uint32_t* b) {
    asm volatile(
        "mma.sync.aligned.m16n8k16.row.col.f16.f16.f16.f16 "
        "{%0,%1}, {%2,%3,%4,%5}, {%6,%7}, {%0,%1};"
        : "+r"(d[0]), "+r"(d[1])
        : "r"(a[0]), "r"(a[1]), "r"(a[2]), "r"(a[3]), "r"(b[0]), "r"(b[1]));
}

// ---------------------------------------------------------------------------
// K0: (merged) Wt transpose/convert + slot softmax
// ---------------------------------------------------------------------------
__global__ void prep_kernel(const float* __restrict__ Wq, const float* __restrict__ Wk,
                            const float* __restrict__ logits) {
    if (blockIdx.x < 128) {
        int idx = blockIdx.x * 256 + threadIdx.x;
        int q = idx >> 8, d = idx & 255;
        g_Wt[0][q * Ddim + d] = __float2half(Wq[d * QKdim + q]);
        g_Wt[1][q * Ddim + d] = __float2half(Wk[d * QKdim + q]);
        return;
    }
    int m = blockIdx.x - 128;
    int tid = threadIdx.x;
    __shared__ float sred[256];
    const float* row = logits + m * Ndim;

    float mx = -1e30f;
    for (int n = tid; n < Ndim; n += 256) mx = fmaxf(mx, row[n]);
    sred[tid] = mx; __syncthreads();
    for (int s = 128; s > 0; s >>= 1) { if (tid < s) sred[tid] = fmaxf(sred[tid], sred[tid + s]); __syncthreads(); }
    mx = sred[0]; __syncthreads();

    float sum = 0.f;
    for (int n = tid; n < Ndim; n += 256) sum += __expf(row[n] - mx);
    sred[tid] = sum; __syncthreads();
    for (int s = 128; s > 0; s >>= 1) { if (tid < s) sred[tid] += sred[tid + s]; __syncthreads(); }
    float inv = 1.0f / sred[0];

    for (int n = tid; n < Ndim; n += 256)
        g_slotw[m * Ndim + n] = __expf(row[n] - mx) * inv;
}

// ---------------------------------------------------------------------------
// K1: projection GEMM (f16 out), register-prefetched
// ---------------------------------------------------------------------------
#define PLDA 40

__global__ __launch_bounds__(256) void proj_kernel(const float* __restrict__ H0,
                                                   const float* __restrict__ X0) {
    const int z = blockIdx.y;
    const float* A = z ? X0 : H0;
    const __half* W = g_Wt[z];
    __half* Out = z ? g_Kh : g_Qh;
    const int row0 = blockIdx.x * 128;

    __shared__ __half As[128 * PLDA];
    __shared__ __half Bs[128 * PLDA];

    const int tid = threadIdx.x;
    const int wid = tid >> 5, lane = tid & 31;
    const int warp_m = wid >> 2, warp_n = wid & 3;
    const int q = lane >> 2, r = lane & 3;

    float c[4][4][4];
#pragma unroll
    for (int mi = 0; mi < 4; mi++)
#pragma unroll
        for (int ni = 0; ni < 4; ni++)
#pragma unroll
            for (int j = 0; j < 4; j++) c[mi][ni][j] = 0.f;

    const int arow = tid >> 3, ac4 = tid & 7;
    const int brow0 = tid >> 4, bcc = tid & 15;

    float4 av[4];
    uint32_t bv[8];
#pragma unroll
    for (int i = 0; i < 4; i++)
        av[i] = *(const float4*)&A[(size_t)(row0 + arow + i * 32) * Ddim + ac4 * 4];
#pragma unroll
    for (int i = 0; i < 8; i++)
        bv[i] = *(const uint32_t*)&W[(brow0 + i * 16) * Ddim + bcc * 2];

    for (int k0 = 0; k0 < Ddim; k0 += 32) {
        __syncthreads();
#pragma unroll
        for (int i = 0; i < 4; i++) {
            __half2 p0, p1;
            p0.x = __float2half(av[i].x); p0.y = __float2half(av[i].y);
            p1.x = __float2half(av[i].z); p1.y = __float2half(av[i].w);
            *(__half2*)&As[(arow + i * 32) * PLDA + ac4 * 4]     = p0;
            *(__half2*)&As[(arow + i * 32) * PLDA + ac4 * 4 + 2] = p1;
        }
#pragma unroll
        for (int i = 0; i < 8; i++)
            *(uint32_t*)&Bs[(brow0 + i * 16) * PLDA + bcc * 2] = bv[i];
        __syncthreads();

        if (k0 + 32 < Ddim) {
#pragma unroll
            for (int i = 0; i < 4; i++)
                av[i] = *(const float4*)&A[(size_t)(row0 + arow + i * 32) * Ddim + k0 + 32 + ac4 * 4];
#pragma unroll
            for (int i = 0; i < 8; i++)
                bv[i] = *(const uint32_t*)&W[(brow0 + i * 16) * Ddim + k0 + 32 + bcc * 2];
        }

#pragma unroll
        for (int ks = 0; ks < 32; ks += 16) {
            uint32_t af[4][4], bfg[4][2];
#pragma unroll
            for (int mi = 0; mi < 4; mi++) {
                const __half* p = &As[(warp_m * 64 + mi * 16 + q) * PLDA + ks + 2 * r];
                af[mi][0] = *(const uint32_t*)p;
                af[mi][1] = *(const uint32_t*)(p + 8 * PLDA);
                af[mi][2] = *(const uint32_t*)(p + 8);
                af[mi][3] = *(const uint32_t*)(p + 8 * PLDA + 8);
            }
#pragma unroll
            for (int ni = 0; ni < 4; ni++) {
                const __half* p = &Bs[(warp_n * 32 + ni * 8 + q) * PLDA + ks + 2 * r];
                bfg[ni][0] = *(const uint32_t*)p;
                bfg[ni][1] = *(const uint32_t*)(p + 8);
            }
#pragma unroll
            for (int mi = 0; mi < 4; mi++)
#pragma unroll
                for (int ni = 0; ni < 4; ni++)
                    mma_f32acc(c[mi][ni], af[mi], bfg[ni]);
        }
    }

#pragma unroll
    for (int mi = 0; mi < 4; mi++) {
        int row = row0 + warp_m * 64 + mi * 16 + q;
#pragma unroll
        for (int ni = 0; ni < 4; ni++) {
            int col = warp_n * 32 + ni * 8 + 2 * r;
            __half2 v0, v1;
            v0.x = __float2half(c[mi][ni][0]); v0.y = __float2half(c[mi][ni][1]);
            v1.x = __float2half(c[mi][ni][2]); v1.y = __float2half(c[mi][ni][3]);
            *(__half2*)&Out[(size_t)row * QKdim + col]        = v0;
            *(__half2*)&Out[(size_t)(row + 8) * QKdim + col]  = v1;
        }
    }
}

// ---------------------------------------------------------------------------
// K2: pipelined sumexp.  grid (32 n-tiles, 8 b), 256 threads.
// ---------------------------------------------------------------------------
#define CEX   (0.08838834764831845f * 1.4426950408889634f)   // 128^-0.5 * log2(e)
#define KLDB  272
#define TILEB (128 * KLDB)

extern __shared__ char s_dyn[];

__device__ __forceinline__ void stage128(uint32_t sdst, const __half* g, int tid) {
#pragma unroll
    for (int i = 0; i < 8; i++) {
        int lin = tid + i * 256;
        int row = lin >> 4, cc = lin & 15;
        CP_ASYNC16(sdst + row * KLDB + cc * 16, g + row * 128 + cc * 8);
    }
}

// exp-drain one mma group g of the previous chunk's f16 accumulators
__device__ __forceinline__ void drain2(const uint32_t* cd, int g, float* rs) {
    uint32_t d0 = cd[g * 2], d1 = cd[g * 2 + 1];
    float2 f0 = __half22float2(*(const __half2*)&d0);
    float2 f1 = __half22float2(*(const __half2*)&d1);
    const int mi = g >> 2;
    rs[mi * 2]     += ex2f(f0.x * CEX) + ex2f(f0.y * CEX);
    rs[mi * 2 + 1] += ex2f(f1.x * CEX) + ex2f(f1.y * CEX);
}

template <int DRAIN>
__device__ __forceinline__ void chunk_body(
    int mc, uint32_t (&cw)[32], uint32_t (&cd)[32], float (&rs)[8],
    const uint32_t (&aaddr)[4], uint32_t kbase,
    const __half* Kg, int tid, uint32_t sK0, uint32_t sK1)
{
#pragma unroll
    for (int kk = 0; kk < 8; kk++) {
        const uint32_t ko = kk * 32;
        uint32_t af[4][4], bq[2][4];
#pragma unroll
        for (int mi = 0; mi < 4; mi++) ldsm_x4(af[mi], aaddr[mi] + ko);
#pragma unroll
        for (int np = 0; np < 2; np++) ldsm_x4(bq[np], kbase + np * 16 * KLDB + ko);
#pragma unroll
        for (int mi = 0; mi < 4; mi++)
#pragma unroll
            for (int ni = 0; ni < 4; ni++) {
                const int ci = (mi * 4 + ni) * 2;
                if (kk == 0) mma_f16_init(&cw[ci], af[mi], &bq[ni >> 1][(ni & 1) * 2]);
                else         mma_f16_acc (&cw[ci], af[mi], &bq[ni >> 1][(ni & 1) * 2]);
            }
        if (DRAIN) { drain2(cd, 2 * kk, rs); drain2(cd, 2 * kk + 1, rs); }
    }
    CP_WAIT0();                 // chunk mc+1 landed (issued last iteration)
    __syncthreads();            // buffer mc free for all + mc+1 visible to all
    if (mc + 2 < 32)
        stage128((mc & 1) ? sK1 : sK0, Kg + (size_t)(mc + 2) * 128 * 128, tid);
    CP_COMMIT();
}

__global__ __launch_bounds__(256, 2) void sumexp_kernel() {
    const uint32_t sb = smem_u32(s_dyn);
    const uint32_t sQ = sb, sK0 = sb + TILEB, sK1 = sb + 2 * TILEB;
    __shared__ float red[128];

    const int n0 = blockIdx.x * 128;
    const int b = blockIdx.y;
    const int tid = threadIdx.x;
    const int wid = tid >> 5, lane = tid & 31;
    const int warp_m = wid >> 2, warp_n = wid & 3;
    const int q = lane >> 2, r = lane & 3;

    const __half* Qg = g_Qh + ((size_t)(b * Ndim) + n0) * QKdim;
    const __half* Kg = g_Kh + (size_t)(b * Ndim) * QKdim;

    stage128(sQ, Qg, tid);
    stage128(sK0, Kg, tid);
    CP_COMMIT();
    stage128(sK1, Kg + 128 * 128, tid);
    CP_COMMIT();
    CP_WAIT1();                 // Q + chunk0 ready
    __syncthreads();

    const int arow = warp_m * 64 + ((lane >> 3) & 1) * 8 + (lane & 7);
    const uint32_t acol = (lane >> 4) * 16;
    uint32_t aaddr[4];
#pragma unroll
    for (int mi = 0; mi < 4; mi++) aaddr[mi] = sQ + (arow + mi * 16) * KLDB + acol;
    const int brow = warp_n * 32 + ((lane >> 4) & 1) * 8 + (lane & 7);
    const uint32_t boff = brow * KLDB + ((lane >> 3) & 1) * 16;

    uint32_t cA[32], cB[32];
    float rs[8];
#pragma unroll
    for (int i = 0; i < 8; i++) rs[i] = 0.f;

    // chunk 0: fill cA, no drain
    chunk_body<0>(0, cA, cB, rs, aaddr, sK0 + boff, Kg, tid, sK0, sK1);
    // chunks 1..30 in role-swapped pairs
    for (int mc = 1; mc < 31; mc += 2) {
        chunk_body<1>(mc,     cB, cA, rs, aaddr, sK1 + boff, Kg, tid, sK0, sK1);
        chunk_body<1>(mc + 1, cA, cB, rs, aaddr, sK0 + boff, Kg, tid, sK0, sK1);
    }
    // chunk 31: fill cB, drain cA
    chunk_body<1>(31, cB, cA, rs, aaddr, sK1 + boff, Kg, tid, sK0, sK1);
    // final drain of chunk 31
#pragma unroll
    for (int g = 0; g < 16; g++) drain2(cB, g, rs);

    // reduce across lanes sharing each row (lane & 3)
#pragma unroll
    for (int i = 0; i < 8; i++) {
        rs[i] += __shfl_xor_sync(0xffffffffu, rs[i], 1);
        rs[i] += __shfl_xor_sync(0xffffffffu, rs[i], 2);
    }
    if (tid < 128) red[tid] = 0.f;
    __syncthreads();
    if (r == 0) {
#pragma unroll
        for (int mi = 0; mi < 4; mi++) {
            atomicAdd(&red[warp_m * 64 + mi * 16 + q],     rs[mi * 2]);
            atomicAdd(&red[warp_m * 64 + mi * 16 + q + 8], rs[mi * 2 + 1]);
        }
    }
    __syncthreads();
    if (tid < 128) g_sumexp[b * Ndim + n0 + tid] = red[tid];
}

// ---------------------------------------------------------------------------
// K3: w_keep = sumexp / sum_n(sumexp)
// ---------------------------------------------------------------------------
__global__ void wkeep_kernel() {
    int b = blockIdx.x;
    int tid = threadIdx.x;
    __shared__ float sm[256];
    float s = 0.f;
    for (int n = tid; n < Ndim; n += 256) s += g_sumexp[b * Ndim + n];
    sm[tid] = s; __syncthreads();
    for (int st = 128; st > 0; st >>= 1) { if (tid < st) sm[tid] += sm[tid + st]; __syncthreads(); }
    float inv = 1.0f / sm[0];
    for (int n = tid; n < Ndim; n += 256)
        g_wkeep[b * Ndim + n] = g_sumexp[b * Ndim + n] * inv;
}

// ---------------------------------------------------------------------------
// K4: norm[b,m] = sum_n slot_w[m,n]*w_keep[b,n]
// ---------------------------------------------------------------------------
__global__ void norm_kernel() {
    int bm = blockIdx.x;
    int b = bm >> 5, m = bm & 31;
    int tid = threadIdx.x;
    __shared__ float sm[256];
    float s = 0.f;
    for (int n = tid; n < Ndim; n += 256)
        s += g_slotw[m * Ndim + n] * g_wkeep[b * Ndim + n];
    sm[tid] = s; __syncthreads();
    for (int st = 128; st > 0; st >>= 1) { if (tid < st) sm[tid] += sm[tid + st]; __syncthreads(); }
    if (tid == 0) g_norm[bm] = sm[0];
}

// ---------------------------------------------------------------------------
// K5: partial out accumulation (deterministic)
// ---------------------------------------------------------------------------
__global__ __launch_bounds__(256) void out_accum_kernel(const float* __restrict__ H0) {
    const int nc = blockIdx.x, b = blockIdx.y;
    const int n0 = nc * 128;
    const int tid = threadIdx.x;
    __shared__ float coefT[128 * 32];

#pragma unroll
    for (int i = 0; i < 16; i++) {
        int lin = tid + i * 256;
        int n = lin >> 5, m = lin & 31;
        coefT[n * 32 + m] = g_slotw[m * Ndim + n0 + n] * g_wkeep[b * Ndim + n0 + n];
    }
    __syncthreads();

    float acc[32];
#pragma unroll
    for (int m = 0; m < 32; m++) acc[m] = 0.f;

    const float* H = H0 + ((size_t)b * Ndim + n0) * Ddim + tid;
#pragma unroll 4
    for (int n = 0; n < 128; n++) {
        float h = H[(size_t)n * Ddim];
        const float4* cp = (const float4*)&coefT[n * 32];
#pragma unroll
        for (int j = 0; j < 8; j++) {
            float4 c4 = cp[j];
            acc[j * 4 + 0] = fmaf(c4.x, h, acc[j * 4 + 0]);
            acc[j * 4 + 1] = fmaf(c4.y, h, acc[j * 4 + 1]);
            acc[j * 4 + 2] = fmaf(c4.z, h, acc[j * 4 + 2]);
            acc[j * 4 + 3] = fmaf(c4.w, h, acc[j * 4 + 3]);
        }
    }

    float* dst = &g_part[(((size_t)b * 32 + nc) * Mdim) * Ddim + tid];
#pragma unroll
    for (int m = 0; m < 32; m++) dst[(size_t)m * Ddim] = acc[m];
}

// ---------------------------------------------------------------------------
// K6: reduce partials + normalize
// ---------------------------------------------------------------------------
__global__ void reduce_out_kernel(float* __restrict__ out) {
    int idx = blockIdx.x * 256 + threadIdx.x;
    int d = idx & 255;
    int m = (idx >> 8) & 31;
    int b = idx >> 13;
    float s = 0.f;
#pragma unroll
    for (int nc = 0; nc < 32; nc++)
        s += g_part[(((size_t)b * 32 + nc) * Mdim + m) * Ddim + d];
    out[idx] = s / (g_norm[b * 32 + m] + 1e-6f);
}

// ---------------------------------------------------------------------------
// launch
// ---------------------------------------------------------------------------
extern "C" void kernel_launch(void* const* d_in, const int* in_sizes, int n_in,
                              void* d_out, int out_size) {
    const float* X0   = (const float*)d_in[0];
    const float* H0   = (const float*)d_in[1];
    const float* Wq   = (const float*)d_in[2];
    const float* Wk   = (const float*)d_in[3];
    const float* slot = (const float*)d_in[4];
    float* out = (float*)d_out;

    const int SMEM_S = 3 * TILEB;   // 104448
    cudaFuncSetAttribute(sumexp_kernel, cudaFuncAttributeMaxDynamicSharedMemorySize, SMEM_S);

    prep_kernel<<<160, 256>>>(Wq, Wk, slot);
    proj_kernel<<<dim3(256, 2), 256>>>(H0, X0);
    sumexp_kernel<<<dim3(32, 8), 256, SMEM_S>>>();
    wkeep_kernel<<<8, 256>>>();
    norm_kernel<<<256, 256>>>();
    out_accum_kernel<<<dim3(32, 8), 256>>>(H0);
    reduce_out_kernel<<<256, 256>>>(out);
    (void)in_sizes; (void)n_in; (void)out_size;
}

// round 5
// speedup vs baseline: 1.0293x; 1.0293x over previous
#include <cuda_runtime.h>
#include <cuda_fp16.h>
#include <cstdint>

// ============================================================================
// B=8, N=4096, D=256, QK=128, M=32
//   Q = H0 @ Wq ; K = X0 @ Wk          (f16 GEMM, e4m3 output)
//   sumexp[b,n] = sum_m exp(scale * Q[b,n,:]·K[b,m,:])     (fp8 MMA)
//   out[b,m,:] = (sum_n slotw[m,n]*sumexp[b,n]*H0[b,n,:])
//              / (sum_n slotw[m,n]*sumexp[b,n] + 1e-6 * sum_n sumexp[b,n])
//   (exactly equivalent to reference: numerator & denominator scaled by T)
// R5: e4m3 S-GEMM (2x tensor rate, half the LDSM/SMEM traffic), epilogue
//     algebra folds away wkeep/norm kernels.
// ============================================================================

#define Bdim 8
#define Ndim 4096
#define Ddim 256
#define QKdim 128
#define Mdim 32

__device__ unsigned char g_Q8[Bdim * Ndim * QKdim];   // 4 MB e4m3
__device__ unsigned char g_K8[Bdim * Ndim * QKdim];   // 4 MB e4m3
__device__ __half g_Wt[2][QKdim * Ddim];
__device__ float g_sumexp[Bdim * Ndim];
__device__ float g_tsum[Bdim * 32];                   // per-tile sumexp totals
__device__ float g_slotw[Mdim * Ndim];
__device__ float g_csum[Bdim * 32 * Mdim];            // per-chunk coef sums
__device__ float g_norm[Bdim * Mdim];                 // final divisor
__device__ float g_part[Bdim * 32 * Mdim * Ddim];     // 8 MB partials

// ---------------------------------------------------------------------------
// helpers
// ---------------------------------------------------------------------------
__device__ __forceinline__ uint32_t smem_u32(const void* p) {
    uint32_t a;
    asm("{ .reg .u64 t; cvta.to.shared.u64 t, %1; cvt.u32.u64 %0, t; }" : "=r"(a) : "l"(p));
    return a;
}
__device__ __forceinline__ float ex2f(float x) {
    float r; asm("ex2.approx.ftz.f32 %0, %1;" : "=f"(r) : "f"(x)); return r;
}
__device__ __forceinline__ uint16_t cvt_e4m3x2(float hi, float lo) {
    uint16_t r;
    asm("cvt.rn.satfinite.e4m3x2.f32 %0, %1, %2;" : "=h"(r) : "f"(hi), "f"(lo));
    return r;   // low byte = lo, high byte = hi
}
#define CP_ASYNC16(dst, src) \
    asm volatile("cp.async.cg.shared.global [%0], [%1], 16;" :: "r"(dst), "l"(src))
#define CP_COMMIT() asm volatile("cp.async.commit_group;" ::: "memory")
#define CP_WAIT1()  asm volatile("cp.async.wait_group 1;" ::: "memory")

__device__ __forceinline__ void ldsm_x4(uint32_t* r, uint32_t addr) {
    asm volatile("ldmatrix.sync.aligned.m8n8.x4.shared.b16 {%0,%1,%2,%3}, [%4];"
                 : "=r"(r[0]), "=r"(r[1]), "=r"(r[2]), "=r"(r[3]) : "r"(addr));
}
// f16 in, f32 acc (projection)
__device__ __forceinline__ void mma_f16(float* c, const uint32_t* a, const uint32_t* b) {
    asm volatile(
        "mma.sync.aligned.m16n8k16.row.col.f32.f16.f16.f32 "
        "{%0,%1,%2,%3}, {%4,%5,%6,%7}, {%8,%9}, {%0,%1,%2,%3};"
        : "+f"(c[0]), "+f"(c[1]), "+f"(c[2]), "+f"(c[3])
        : "r"(a[0]), "r"(a[1]), "r"(a[2]), "r"(a[3]), "r"(b[0]), "r"(b[1]));
}
// e4m3 in, f32 acc (S kernel)
__device__ __forceinline__ void mma_fp8(float* c, const uint32_t* a, const uint32_t* b) {
    asm volatile(
        "mma.sync.aligned.m16n8k32.row.col.f32.e4m3.e4m3.f32 "
        "{%0,%1,%2,%3}, {%4,%5,%6,%7}, {%8,%9}, {%0,%1,%2,%3};"
        : "+f"(c[0]), "+f"(c[1]), "+f"(c[2]), "+f"(c[3])
        : "r"(a[0]), "r"(a[1]), "r"(a[2]), "r"(a[3]), "r"(b[0]), "r"(b[1]));
}

// ---------------------------------------------------------------------------
// K0: Wt transpose/convert + slot softmax (merged)
// ---------------------------------------------------------------------------
__global__ void prep_kernel(const float* __restrict__ Wq, const float* __restrict__ Wk,
                            const float* __restrict__ logits) {
    if (blockIdx.x < 128) {
        int idx = blockIdx.x * 256 + threadIdx.x;
        int q = idx >> 8, d = idx & 255;
        g_Wt[0][q * Ddim + d] = __float2half(Wq[d * QKdim + q]);
        g_Wt[1][q * Ddim + d] = __float2half(Wk[d * QKdim + q]);
        return;
    }
    int m = blockIdx.x - 128;
    int tid = threadIdx.x;
    __shared__ float sred[256];
    const float* row = logits + m * Ndim;

    float mx = -1e30f;
    for (int n = tid; n < Ndim; n += 256) mx = fmaxf(mx, row[n]);
    sred[tid] = mx; __syncthreads();
    for (int s = 128; s > 0; s >>= 1) { if (tid < s) sred[tid] = fmaxf(sred[tid], sred[tid + s]); __syncthreads(); }
    mx = sred[0]; __syncthreads();

    float sum = 0.f;
    for (int n = tid; n < Ndim; n += 256) sum += __expf(row[n] - mx);
    sred[tid] = sum; __syncthreads();
    for (int s = 128; s > 0; s >>= 1) { if (tid < s) sred[tid] += sred[tid + s]; __syncthreads(); }
    float inv = 1.0f / sred[0];

    for (int n = tid; n < Ndim; n += 256)
        g_slotw[m * Ndim + n] = __expf(row[n] - mx) * inv;
}

// ---------------------------------------------------------------------------
// K1: projection GEMM (f16 compute, e4m3 output), register-prefetched
// ---------------------------------------------------------------------------
#define PLDA 40

__global__ __launch_bounds__(256) void proj_kernel(const float* __restrict__ H0,
                                                   const float* __restrict__ X0) {
    const int z = blockIdx.y;
    const float* A = z ? X0 : H0;
    const __half* W = g_Wt[z];
    unsigned char* Out = z ? g_K8 : g_Q8;
    const int row0 = blockIdx.x * 128;

    __shared__ __half As[128 * PLDA];
    __shared__ __half Bs[128 * PLDA];

    const int tid = threadIdx.x;
    const int wid = tid >> 5, lane = tid & 31;
    const int warp_m = wid >> 2, warp_n = wid & 3;
    const int q = lane >> 2, r = lane & 3;

    float c[4][4][4];
#pragma unroll
    for (int mi = 0; mi < 4; mi++)
#pragma unroll
        for (int ni = 0; ni < 4; ni++)
#pragma unroll
            for (int j = 0; j < 4; j++) c[mi][ni][j] = 0.f;

    const int arow = tid >> 3, ac4 = tid & 7;
    const int brow0 = tid >> 4, bcc = tid & 15;

    float4 av[4];
    uint32_t bv[8];
#pragma unroll
    for (int i = 0; i < 4; i++)
        av[i] = *(const float4*)&A[(size_t)(row0 + arow + i * 32) * Ddim + ac4 * 4];
#pragma unroll
    for (int i = 0; i < 8; i++)
        bv[i] = *(const uint32_t*)&W[(brow0 + i * 16) * Ddim + bcc * 2];

    for (int k0 = 0; k0 < Ddim; k0 += 32) {
        __syncthreads();
#pragma unroll
        for (int i = 0; i < 4; i++) {
            __half2 p0, p1;
            p0.x = __float2half(av[i].x); p0.y = __float2half(av[i].y);
            p1.x = __float2half(av[i].z); p1.y = __float2half(av[i].w);
            *(__half2*)&As[(arow + i * 32) * PLDA + ac4 * 4]     = p0;
            *(__half2*)&As[(arow + i * 32) * PLDA + ac4 * 4 + 2] = p1;
        }
#pragma unroll
        for (int i = 0; i < 8; i++)
            *(uint32_t*)&Bs[(brow0 + i * 16) * PLDA + bcc * 2] = bv[i];
        __syncthreads();

        if (k0 + 32 < Ddim) {
#pragma unroll
            for (int i = 0; i < 4; i++)
                av[i] = *(const float4*)&A[(size_t)(row0 + arow + i * 32) * Ddim + k0 + 32 + ac4 * 4];
#pragma unroll
            for (int i = 0; i < 8; i++)
                bv[i] = *(const uint32_t*)&W[(brow0 + i * 16) * Ddim + k0 + 32 + bcc * 2];
        }

#pragma unroll
        for (int ks = 0; ks < 32; ks += 16) {
            uint32_t af[4][4], bfg[4][2];
#pragma unroll
            for (int mi = 0; mi < 4; mi++) {
                const __half* p = &As[(warp_m * 64 + mi * 16 + q) * PLDA + ks + 2 * r];
                af[mi][0] = *(const uint32_t*)p;
                af[mi][1] = *(const uint32_t*)(p + 8 * PLDA);
                af[mi][2] = *(const uint32_t*)(p + 8);
                af[mi][3] = *(const uint32_t*)(p + 8 * PLDA + 8);
            }
#pragma unroll
            for (int ni = 0; ni < 4; ni++) {
                const __half* p = &Bs[(warp_n * 32 + ni * 8 + q) * PLDA + ks + 2 * r];
                bfg[ni][0] = *(const uint32_t*)p;
                bfg[ni][1] = *(const uint32_t*)(p + 8);
            }
#pragma unroll
            for (int mi = 0; mi < 4; mi++)
#pragma unroll
                for (int ni = 0; ni < 4; ni++)
                    mma_f16(c[mi][ni], af[mi], bfg[ni]);
        }
    }

    // epilogue: f32 -> e4m3 pairs (cols 2r, 2r+1)
#pragma unroll
    for (int mi = 0; mi < 4; mi++) {
        int row = row0 + warp_m * 64 + mi * 16 + q;
#pragma unroll
        for (int ni = 0; ni < 4; ni++) {
            int col = warp_n * 32 + ni * 8 + 2 * r;
            *(uint16_t*)&Out[(size_t)row * QKdim + col] =
                cvt_e4m3x2(c[mi][ni][1], c[mi][ni][0]);
            *(uint16_t*)&Out[(size_t)(row + 8) * QKdim + col] =
                cvt_e4m3x2(c[mi][ni][3], c[mi][ni][2]);
        }
    }
}

// ---------------------------------------------------------------------------
// K2: sumexp via fp8 MMA.  grid (32 n-tiles, 8 b), 256 threads.
//   128x128 fp8 tiles: 128 B/row, smem stride 144 (conflict-free ldmatrix).
// ---------------------------------------------------------------------------
#define CEX   (0.08838834764831845f * 1.4426950408889634f)   // 128^-0.5 * log2(e)
#define KLD8  144
#define TILE8 (128 * KLD8)          // 18432 bytes

extern __shared__ char s_dyn[];

__device__ __forceinline__ void stage128_8(uint32_t sdst, const unsigned char* g, int tid) {
#pragma unroll
    for (int i = 0; i < 4; i++) {
        int lin = tid + i * 256;
        int row = lin >> 3, cc = lin & 7;
        CP_ASYNC16(sdst + row * KLD8 + cc * 16, g + row * 128 + cc * 16);
    }
}

__global__ __launch_bounds__(256, 2) void sumexp_kernel() {
    const uint32_t sb = smem_u32(s_dyn);
    const uint32_t sQ = sb, sK0 = sb + TILE8, sK1 = sb + 2 * TILE8;
    __shared__ float red[128];

    const int n0 = blockIdx.x * 128;
    const int b = blockIdx.y;
    const int tid = threadIdx.x;
    const int wid = tid >> 5, lane = tid & 31;
    const int warp_m = wid >> 2, warp_n = wid & 3;
    const int q = lane >> 2, r = lane & 3;

    const unsigned char* Qg = g_Q8 + ((size_t)(b * Ndim) + n0) * QKdim;
    const unsigned char* Kg = g_K8 + (size_t)(b * Ndim) * QKdim;

    stage128_8(sQ, Qg, tid);
    stage128_8(sK0, Kg, tid);
    CP_COMMIT();
    stage128_8(sK1, Kg + 128 * 128, tid);
    CP_COMMIT();
    CP_WAIT1();                 // Q + chunk0 ready
    __syncthreads();

    // ldmatrix bases. A: 16-row x 32-byte footprint per (mi, k-step)
    const int arow = warp_m * 64 + ((lane >> 3) & 1) * 8 + (lane & 7);
    const uint32_t acol = (lane >> 4) * 16;
    uint32_t aaddr[4];
#pragma unroll
    for (int mi = 0; mi < 4; mi++) aaddr[mi] = sQ + (arow + mi * 16) * KLD8 + acol;
    const int brow = warp_n * 32 + ((lane >> 4) & 1) * 8 + (lane & 7);
    const uint32_t boff = brow * KLD8 + ((lane >> 3) & 1) * 16;

    float rs[8];
#pragma unroll
    for (int i = 0; i < 8; i++) rs[i] = 0.f;

    for (int mc = 0; mc < 32; mc++) {
        const uint32_t kbase = ((mc & 1) ? sK1 : sK0) + boff;

        float c[4][4][4];
#pragma unroll
        for (int mi = 0; mi < 4; mi++)
#pragma unroll
            for (int ni = 0; ni < 4; ni++)
#pragma unroll
                for (int j = 0; j < 4; j++) c[mi][ni][j] = 0.f;

#pragma unroll
        for (int kk = 0; kk < 4; kk++) {
            const uint32_t ko = kk * 32;
            uint32_t af[4][4], bq[2][4];
#pragma unroll
            for (int mi = 0; mi < 4; mi++) ldsm_x4(af[mi], aaddr[mi] + ko);
#pragma unroll
            for (int np = 0; np < 2; np++) ldsm_x4(bq[np], kbase + np * 16 * KLD8 + ko);
#pragma unroll
            for (int mi = 0; mi < 4; mi++)
#pragma unroll
                for (int ni = 0; ni < 4; ni++)
                    mma_fp8(c[mi][ni], af[mi], &bq[ni >> 1][(ni & 1) * 2]);
        }

        // exp + row accumulate
#pragma unroll
        for (int mi = 0; mi < 4; mi++) {
            float s0 = 0.f, s1 = 0.f;
#pragma unroll
            for (int ni = 0; ni < 4; ni++) {
                s0 += ex2f(c[mi][ni][0] * CEX) + ex2f(c[mi][ni][1] * CEX);
                s1 += ex2f(c[mi][ni][2] * CEX) + ex2f(c[mi][ni][3] * CEX);
            }
            rs[mi * 2] += s0; rs[mi * 2 + 1] += s1;
        }

        __syncthreads();
        if (mc + 2 < 32)
            stage128_8((mc & 1) ? sK1 : sK0, Kg + (size_t)(mc + 2) * 128 * 128, tid);
        CP_COMMIT();
        CP_WAIT1();
        __syncthreads();
    }

    // reduce across lanes sharing each row (lane & 3)
#pragma unroll
    for (int i = 0; i < 8; i++) {
        rs[i] += __shfl_xor_sync(0xffffffffu, rs[i], 1);
        rs[i] += __shfl_xor_sync(0xffffffffu, rs[i], 2);
    }
    if (tid < 128) red[tid] = 0.f;
    __syncthreads();
    if (r == 0) {
#pragma unroll
        for (int mi = 0; mi < 4; mi++) {
            atomicAdd(&red[warp_m * 64 + mi * 16 + q],     rs[mi * 2]);
            atomicAdd(&red[warp_m * 64 + mi * 16 + q + 8], rs[mi * 2 + 1]);
        }
    }
    __syncthreads();
    if (tid < 128) g_sumexp[b * Ndim + n0 + tid] = red[tid];
    __syncthreads();
    // deterministic tile-sum for T[b]
    for (int s = 64; s > 0; s >>= 1) {
        if (tid < s) red[tid] += red[tid + s];
        __syncthreads();
    }
    if (tid == 0) g_tsum[b * 32 + blockIdx.x] = red[0];
}

// ---------------------------------------------------------------------------
// K3: partial out accumulation + per-chunk coef sums (deterministic)
// ---------------------------------------------------------------------------
__global__ __launch_bounds__(256) void out_accum_kernel(const float* __restrict__ H0) {
    const int nc = blockIdx.x, b = blockIdx.y;
    const int n0 = nc * 128;
    const int tid = threadIdx.x;
    __shared__ float coefT[128 * 32];   // [n][m]
    __shared__ float sgrp[8 * 32];

#pragma unroll
    for (int i = 0; i < 16; i++) {
        int lin = tid + i * 256;
        int n = lin >> 5, m = lin & 31;
        coefT[n * 32 + m] = g_slotw[m * Ndim + n0 + n] * g_sumexp[b * Ndim + n0 + n];
    }
    __syncthreads();

    // per-chunk coef sums: csum[m] = sum_n coefT[n][m], deterministic order
    {
        const int m = tid & 31, g = tid >> 5;
        float s = 0.f;
#pragma unroll
        for (int j = 0; j < 16; j++) s += coefT[(g + j * 8) * 32 + m];
        sgrp[g * 32 + m] = s;
    }
    __syncthreads();
    if (tid < 32) {
        float s = 0.f;
#pragma unroll
        for (int g = 0; g < 8; g++) s += sgrp[g * 32 + tid];
        g_csum[(b * 32 + nc) * 32 + tid] = s;
    }

    float acc[32];
#pragma unroll
    for (int m = 0; m < 32; m++) acc[m] = 0.f;

    const float* H = H0 + ((size_t)b * Ndim + n0) * Ddim + tid;
#pragma unroll 4
    for (int n = 0; n < 128; n++) {
        float h = H[(size_t)n * Ddim];
        const float4* cp = (const float4*)&coefT[n * 32];
#pragma unroll
        for (int j = 0; j < 8; j++) {
            float4 c4 = cp[j];
            acc[j * 4 + 0] = fmaf(c4.x, h, acc[j * 4 + 0]);
            acc[j * 4 + 1] = fmaf(c4.y, h, acc[j * 4 + 1]);
            acc[j * 4 + 2] = fmaf(c4.z, h, acc[j * 4 + 2]);
            acc[j * 4 + 3] = fmaf(c4.w, h, acc[j * 4 + 3]);
        }
    }

    float* dst = &g_part[(((size_t)b * 32 + nc) * Mdim) * Ddim + tid];
#pragma unroll
    for (int m = 0; m < 32; m++) dst[(size_t)m * Ddim] = acc[m];
}

// ---------------------------------------------------------------------------
// K4: micro — final divisor per (b,m): norm = sum_nc csum + 1e-6 * T[b]
// ---------------------------------------------------------------------------
__global__ void micro_kernel() {
    int bm = threadIdx.x;       // 256 threads, 1 block
    int b = bm >> 5, m = bm & 31;
    float T = 0.f;
#pragma unroll
    for (int t = 0; t < 32; t++) T += g_tsum[b * 32 + t];
    float s = 0.f;
#pragma unroll
    for (int nc = 0; nc < 32; nc++) s += g_csum[(b * 32 + nc) * 32 + m];
    g_norm[bm] = s + 1e-6f * T;
}

// ---------------------------------------------------------------------------
// K5: reduce partials + divide
// ---------------------------------------------------------------------------
__global__ void reduce_out_kernel(float* __restrict__ out) {
    int idx = blockIdx.x * 256 + threadIdx.x;
    int d = idx & 255;
    int m = (idx >> 8) & 31;
    int b = idx >> 13;
    float s = 0.f;
#pragma unroll
    for (int nc = 0; nc < 32; nc++)
        s += g_part[(((size_t)b * 32 + nc) * Mdim + m) * Ddim + d];
    out[idx] = s / g_norm[b * 32 + m];
}

// ---------------------------------------------------------------------------
// launch
// ---------------------------------------------------------------------------
extern "C" void kernel_launch(void* const* d_in, const int* in_sizes, int n_in,
                              void* d_out, int out_size) {
    const float* X0   = (const float*)d_in[0];
    const float* H0   = (const float*)d_in[1];
    const float* Wq   = (const float*)d_in[2];
    const float* Wk   = (const float*)d_in[3];
    const float* slot = (const float*)d_in[4];
    float* out = (float*)d_out;

    const int SMEM_S = 3 * TILE8;   // 55296
    cudaFuncSetAttribute(sumexp_kernel, cudaFuncAttributeMaxDynamicSharedMemorySize, SMEM_S);

    prep_kernel<<<160, 256>>>(Wq, Wk, slot);
    proj_kernel<<<dim3(256, 2), 256>>>(H0, X0);
    sumexp_kernel<<<dim3(32, 8), 256, SMEM_S>>>();
    out_accum_kernel<<<dim3(32, 8), 256>>>(H0);
    micro_kernel<<<1, 256>>>();
    reduce_out_kernel<<<256, 256>>>(out);
    (void)in_sizes; (void)n_in; (void)out_size;
}